// round 15
// baseline (speedup 1.0000x reference)
#include <cuda_runtime.h>

#define N_NODES 50000
#define N_EDGES 500000
#define N_GRAPHS 2000
#define HID 145
#define PITCH 148          // row pitch (16B multiple: 148*4 = 592)
#define NCH 37             // float4 chunks per row
#define WSP 160            // Ws shared pitch: 80 col-pairs
#define HID2 72
#define N_LAYERS 4
#define EPS 1e-5f
#define TILE_M 64
#define SCAN_NB 49         // ceil(50000/1024)
#define NPW 8              // nodes per warp in gather

// ---- scratch (static device globals; +64 pad for overhung tile loads) ----
__device__ __align__(16) float  g_h  [(size_t)N_NODES * PITCH + 64];
__device__ __align__(16) float  g_hw [(size_t)N_NODES * PITCH + 64];
__device__ __align__(16) float  g_agg[(size_t)N_NODES * PITCH + 64];
__device__ float  g_dis[N_NODES];
__device__ int    g_deg[N_NODES];
__device__ int    g_rowptr[N_NODES + 1];
__device__ int    g_cursor[N_NODES];
__device__ int    g_bsum[64];
__device__ int    g_csr_src[N_EDGES];
__device__ float  g_csr_w[N_EDGES];
__device__ double g_stats[2 * PITCH];
__device__ __align__(16) float g_bnA[192];
__device__ __align__(16) float g_bnB[192];

// packed f32x2 FMA (PTX-only; ptxas never auto-fuses)
__device__ __forceinline__ float2 ffma2(float2 a, float2 b, float2 c) {
    unsigned long long ua, ub, uc, ud;
    ua = *reinterpret_cast<unsigned long long*>(&a);
    ub = *reinterpret_cast<unsigned long long*>(&b);
    uc = *reinterpret_cast<unsigned long long*>(&c);
    asm("fma.rn.f32x2 %0, %1, %2, %3;" : "=l"(ud) : "l"(ua), "l"(ub), "l"(uc));
    return *reinterpret_cast<float2*>(&ud);
}

// ---------------- degree / CSR build ----------------
__global__ void k_deg_zero() {
    int i = blockIdx.x * blockDim.x + threadIdx.x;
    if (i < N_NODES) g_deg[i] = 0;
}

__global__ void k_deg_count(const int* __restrict__ ei) {
    int e = blockIdx.x * blockDim.x + threadIdx.x;
    if (e < N_EDGES) atomicAdd(&g_deg[ei[N_EDGES + e]], 1);  // target = col
}

__global__ void k_dis() {
    int i = blockIdx.x * blockDim.x + threadIdx.x;
    if (i < N_NODES) g_dis[i] = rsqrtf((float)(g_deg[i] + 1));  // +1 self loop
}

// ---- 3-phase parallel scan over degrees -> rowptr (exclusive), cursor ----
__global__ void k_scan1() {
    __shared__ int wsum[32];
    const int tid = threadIdx.x;
    const int i = blockIdx.x * 1024 + tid;
    int v = (i < N_NODES) ? g_deg[i] : 0;
    int lane = tid & 31, w = tid >> 5;
    int s = v;
#pragma unroll
    for (int o = 1; o < 32; o <<= 1) {
        int t = __shfl_up_sync(0xFFFFFFFFu, s, o);
        if (lane >= o) s += t;
    }
    if (lane == 31) wsum[w] = s;
    __syncthreads();
    if (w == 0) {
        int t = wsum[lane];
#pragma unroll
        for (int o = 1; o < 32; o <<= 1) {
            int u = __shfl_up_sync(0xFFFFFFFFu, t, o);
            if (lane >= o) t += u;
        }
        wsum[lane] = t;
    }
    __syncthreads();
    int excl = s - v + (w > 0 ? wsum[w - 1] : 0);
    if (i < N_NODES) g_rowptr[i] = excl;
    if (tid == 1023) g_bsum[blockIdx.x] = excl + v;   // block total
}

__global__ void k_scan2() {
    __shared__ int sh[64];
    int tid = threadIdx.x;
    if (tid < SCAN_NB) sh[tid] = g_bsum[tid];
    __syncthreads();
    if (tid == 0) {
        int acc = 0;
        for (int b = 0; b < SCAN_NB; b++) { int t = sh[b]; sh[b] = acc; acc += t; }
    }
    __syncthreads();
    if (tid < SCAN_NB) g_bsum[tid] = sh[tid];
}

__global__ void k_scan3() {
    int i = blockIdx.x * 1024 + threadIdx.x;
    if (i < N_NODES) {
        int v = g_rowptr[i] + g_bsum[blockIdx.x];
        g_rowptr[i] = v;
        g_cursor[i] = v;
    }
    if (i == 0) g_rowptr[N_NODES] = N_EDGES;
}

__global__ void k_fill(const int* __restrict__ ei) {
    int e = blockIdx.x * blockDim.x + threadIdx.x;
    if (e >= N_EDGES) return;
    int r = ei[e];
    int c = ei[N_EDGES + e];
    int pos = atomicAdd(&g_cursor[c], 1);
    g_csr_src[pos] = r;
    g_csr_w[pos]   = g_dis[r] * g_dis[c];
}

// ---------------- GEMM: hw = h @ Wc[l], fused A-generation ----------------
// mode 0: A = emb[x[row]]  (embedding gather; also materializes g_h)
// mode 1: A = relu(g_agg*bnA+bnB) + g_h_old  (prev layer's epilogue; updates g_h)
// Block: 64 rows x 160 cols, 256 threads. Thread: 4 rows x 5 col-pairs (f32x2).
__global__ void __launch_bounds__(256) k_gemm(const float* __restrict__ Wl,
                                              const int*   __restrict__ x,
                                              const float* __restrict__ emb,
                                              int mode) {
    __shared__ float As[TILE_M * 64];       // 16 KB
    __shared__ float Ws[64 * WSP];          // 40 KB
    const int tid  = threadIdx.x;
    const int ct   = tid & 15;
    const int rt   = tid >> 4;
    const int row0 = blockIdx.x * TILE_M;

    if (blockIdx.x == 0)
        for (int i = tid; i < 2 * PITCH; i += 256) g_stats[i] = 0.0;  // zero BN stats

    float2 acc[4][5];
#pragma unroll
    for (int r = 0; r < 4; r++)
#pragma unroll
        for (int j = 0; j < 5; j++) acc[r][j] = make_float2(0.0f, 0.0f);

#pragma unroll 1
    for (int kt = 0; kt < 160; kt += 64) {
        const int kmax = (160 - kt) < 64 ? (160 - kt) : 64;   // 64,64,32
        __syncthreads();
        // A tile [64 x 64]: 1024 float4 slots, 4 per thread
#pragma unroll
        for (int q = 0; q < 4; q++) {
            int fi   = tid + 256 * q;
            int row  = fi >> 4;
            int kq   = fi & 15;
            int col0 = kt + kq * 4;
            int r    = row0 + row;
            float4 v = make_float4(0.f, 0.f, 0.f, 0.f);
            if (r < N_NODES && col0 < 160) {
                if (mode == 0) {
                    int base = x[r] * HID;
                    v.x = (col0     < HID) ? emb[base + col0]     : 0.0f;
                    v.y = (col0 + 1 < HID) ? emb[base + col0 + 1] : 0.0f;
                    v.z = (col0 + 2 < HID) ? emb[base + col0 + 2] : 0.0f;
                    v.w = (col0 + 3 < HID) ? emb[base + col0 + 3] : 0.0f;
                    if (col0 < PITCH) *(float4*)&g_h[(size_t)r * PITCH + col0] = v;
                } else {
                    float4 va = *(const float4*)&g_agg[(size_t)r * PITCH + col0];
                    float4 vh = *(const float4*)&g_h  [(size_t)r * PITCH + col0];
                    float4 A  = *(const float4*)&g_bnA[col0];
                    float4 B  = *(const float4*)&g_bnB[col0];
                    v.x = fmaxf(va.x * A.x + B.x, 0.0f) + vh.x;
                    v.y = fmaxf(va.y * A.y + B.y, 0.0f) + vh.y;
                    v.z = fmaxf(va.z * A.z + B.z, 0.0f) + vh.z;
                    v.w = fmaxf(va.w * A.w + B.w, 0.0f) + vh.w;
                    if (col0 < PITCH) *(float4*)&g_h[(size_t)r * PITCH + col0] = v;
                }
            }
            *(float4*)&As[row * 64 + kq * 4] = v;
        }
        // W tile [kmax x 160], zero outside live range
        for (int i = tid; i < kmax * WSP; i += 256) {
            int kk = i / WSP, c = i - kk * WSP;
            int kg = kt + kk;
            Ws[i] = (kg < HID && c < HID) ? Wl[kg * HID + c] : 0.0f;
        }
        __syncthreads();

#pragma unroll 4
        for (int k4 = 0; k4 < kmax; k4 += 4) {
            float4 av0 = *(const float4*)&As[(rt * 4 + 0) * 64 + k4];
            float4 av1 = *(const float4*)&As[(rt * 4 + 1) * 64 + k4];
            float4 av2 = *(const float4*)&As[(rt * 4 + 2) * 64 + k4];
            float4 av3 = *(const float4*)&As[(rt * 4 + 3) * 64 + k4];
#pragma unroll
            for (int kk = 0; kk < 4; kk++) {
                float2 b[5];
#pragma unroll
                for (int j = 0; j < 5; j++)
                    b[j] = *(const float2*)&Ws[(k4 + kk) * WSP + 2 * ct + 32 * j];
                float a0 = ((const float*)&av0)[kk];
                float a1 = ((const float*)&av1)[kk];
                float a2 = ((const float*)&av2)[kk];
                float a3 = ((const float*)&av3)[kk];
                float2 p0 = make_float2(a0, a0), p1 = make_float2(a1, a1);
                float2 p2 = make_float2(a2, a2), p3 = make_float2(a3, a3);
#pragma unroll
                for (int j = 0; j < 5; j++) {
                    acc[0][j] = ffma2(p0, b[j], acc[0][j]);
                    acc[1][j] = ffma2(p1, b[j], acc[1][j]);
                    acc[2][j] = ffma2(p2, b[j], acc[2][j]);
                    acc[3][j] = ffma2(p3, b[j], acc[3][j]);
                }
            }
        }
    }

#pragma unroll
    for (int rr = 0; rr < 4; rr++) {
        int r = row0 + rt * 4 + rr;
        if (r >= N_NODES) continue;
#pragma unroll
        for (int j = 0; j < 5; j++) {
            int c0 = 2 * ct + 32 * j;
            if (c0 >= PITCH) continue;
            *(float2*)&g_hw[(size_t)r * PITCH + c0] = acc[rr][j];
        }
    }
}

// ------- aggregation: 8 nodes per warp, register stats, one block reduce ------
// 512 threads = 16 warps x NPW nodes = 128 nodes/block; 391 blocks.
__global__ void __launch_bounds__(512) k_gather(const float* __restrict__ bcl) {
    __shared__ float sums1[16][PITCH];
    __shared__ float sums2[16][PITCH];
    const int wib  = threadIdx.x >> 5;
    const int lane = threadIdx.x & 31;
    const int warpId = blockIdx.x * 16 + wib;
    const bool tail = lane < NCH - 32;

    float s1a[4] = {0.f, 0.f, 0.f, 0.f}, s2a[4] = {0.f, 0.f, 0.f, 0.f};
    float s1b[4] = {0.f, 0.f, 0.f, 0.f}, s2b[4] = {0.f, 0.f, 0.f, 0.f};

#pragma unroll 1
    for (int i = 0; i < NPW; i++) {
        int node = warpId * NPW + i;
        if (node < N_NODES) {
            const int beg = g_rowptr[node];
            const int end = g_rowptr[node + 1];
            float d  = g_dis[node];
            float sw = d * d;                 // self-loop weight

            const float4* own = (const float4*)g_hw + (size_t)node * NCH;

            float4 a0, a1 = make_float4(0.f, 0.f, 0.f, 0.f);
            {
                float4 v = own[lane];
                int c = lane * 4;
                a0.x = bcl[c]     + sw * v.x;
                a0.y = bcl[c + 1] + sw * v.y;
                a0.z = bcl[c + 2] + sw * v.z;
                a0.w = bcl[c + 3] + sw * v.w;
                if (tail) {
                    float4 v2 = own[32 + lane];
                    int c2 = 128 + lane * 4;
                    a1.x = (c2     < HID ? bcl[c2]     : 0.0f) + sw * v2.x;
                    a1.y = (c2 + 1 < HID ? bcl[c2 + 1] : 0.0f) + sw * v2.y;
                    a1.z = (c2 + 2 < HID ? bcl[c2 + 2] : 0.0f) + sw * v2.z;
                    a1.w = (c2 + 3 < HID ? bcl[c2 + 3] : 0.0f) + sw * v2.w;
                }
            }

            int e = beg;
            for (; e + 3 < end; e += 4) {     // 4x unroll (deg~10)
                int   s0 = g_csr_src[e],     s1 = g_csr_src[e + 1];
                int   s2 = g_csr_src[e + 2], s3 = g_csr_src[e + 3];
                float w0 = g_csr_w[e],       w1 = g_csr_w[e + 1];
                float w2 = g_csr_w[e + 2],   w3 = g_csr_w[e + 3];
                const float4* sp0 = (const float4*)g_hw + (size_t)s0 * NCH;
                const float4* sp1 = (const float4*)g_hw + (size_t)s1 * NCH;
                const float4* sp2 = (const float4*)g_hw + (size_t)s2 * NCH;
                const float4* sp3 = (const float4*)g_hw + (size_t)s3 * NCH;
                float4 v0 = sp0[lane], v1 = sp1[lane], v2 = sp2[lane], v3 = sp3[lane];
                float4 u0, u1, u2, u3;
                if (tail) { u0 = sp0[32 + lane]; u1 = sp1[32 + lane];
                            u2 = sp2[32 + lane]; u3 = sp3[32 + lane]; }
                a0.x += w0 * v0.x + w1 * v1.x + w2 * v2.x + w3 * v3.x;
                a0.y += w0 * v0.y + w1 * v1.y + w2 * v2.y + w3 * v3.y;
                a0.z += w0 * v0.z + w1 * v1.z + w2 * v2.z + w3 * v3.z;
                a0.w += w0 * v0.w + w1 * v1.w + w2 * v2.w + w3 * v3.w;
                if (tail) {
                    a1.x += w0 * u0.x + w1 * u1.x + w2 * u2.x + w3 * u3.x;
                    a1.y += w0 * u0.y + w1 * u1.y + w2 * u2.y + w3 * u3.y;
                    a1.z += w0 * u0.z + w1 * u1.z + w2 * u2.z + w3 * u3.z;
                    a1.w += w0 * u0.w + w1 * u1.w + w2 * u2.w + w3 * u3.w;
                }
            }
            for (; e < end; e++) {
                int   s0 = g_csr_src[e];
                float w0 = g_csr_w[e];
                const float4* sp0 = (const float4*)g_hw + (size_t)s0 * NCH;
                float4 v0 = sp0[lane];
                a0.x += w0 * v0.x; a0.y += w0 * v0.y; a0.z += w0 * v0.z; a0.w += w0 * v0.w;
                if (tail) {
                    float4 u0 = sp0[32 + lane];
                    a1.x += w0 * u0.x; a1.y += w0 * u0.y; a1.z += w0 * u0.z; a1.w += w0 * u0.w;
                }
            }

            float4* dst = (float4*)g_agg + (size_t)node * NCH;
            dst[lane] = a0;
            if (tail) dst[32 + lane] = a1;

            // accumulate per-lane channel stats in registers (float partials)
            s1a[0] += a0.x; s2a[0] += a0.x * a0.x;
            s1a[1] += a0.y; s2a[1] += a0.y * a0.y;
            s1a[2] += a0.z; s2a[2] += a0.z * a0.z;
            s1a[3] += a0.w; s2a[3] += a0.w * a0.w;
            if (tail) {
                s1b[0] += a1.x; s2b[0] += a1.x * a1.x;
                s1b[1] += a1.y; s2b[1] += a1.y * a1.y;
                s1b[2] += a1.z; s2b[2] += a1.z * a1.z;
                s1b[3] += a1.w; s2b[3] += a1.w * a1.w;
            }
        }
    }

    // stage per-warp partials (lane l owns channels 4l..4l+3 and 128+4l..+3)
    {
        int c = lane * 4;
#pragma unroll
        for (int j = 0; j < 4; j++) {
            sums1[wib][c + j] = s1a[j];
            sums2[wib][c + j] = s2a[j];
        }
        if (tail) {
            int c2 = 128 + lane * 4;
#pragma unroll
            for (int j = 0; j < 4; j++) {
                sums1[wib][c2 + j] = s1b[j];
                sums2[wib][c2 + j] = s2b[j];
            }
        }
    }
    __syncthreads();
    int c = threadIdx.x;
    if (c < PITCH) {
        double t1 = 0.0, t2 = 0.0;
#pragma unroll
        for (int k = 0; k < 16; k++) {
            t1 += (double)sums1[k][c];
            t2 += (double)sums2[k][c];
        }
        atomicAdd(&g_stats[c], t1);
        atomicAdd(&g_stats[PITCH + c], t2);
    }
}

__global__ void k_bnab(const float* __restrict__ gammal, const float* __restrict__ betal) {
    int c = threadIdx.x;
    if (c >= 192) return;
    if (c < HID) {
        double mu  = g_stats[c] / (double)N_NODES;
        double var = g_stats[PITCH + c] / (double)N_NODES - mu * mu;
        if (var < 0.0) var = 0.0;
        float a = gammal[c] * rsqrtf((float)var + EPS);
        g_bnA[c] = a;
        g_bnB[c] = betal[c] - (float)mu * a;
    } else {
        g_bnA[c] = 0.0f;
        g_bnB[c] = 0.0f;
    }
}

// ------- global mean pool (fused final BN apply) + MLP head -------
__global__ void k_pool(const int* __restrict__ batch,
                       const float* __restrict__ W1, const float* __restrict__ b1,
                       const float* __restrict__ W2, const float* __restrict__ b2,
                       float* __restrict__ out) {
    const int g   = blockIdx.x;
    const int tid = threadIdx.x;
    __shared__ float hg[HID];
    __shared__ float p[HID2];

    int lo, hi;
    { int a = 0, b = N_NODES;
      while (a < b) { int m = (a + b) >> 1; if (batch[m] < g) a = m + 1; else b = m; }
      lo = a; }
    { int a = lo, b = N_NODES;
      while (a < b) { int m = (a + b) >> 1; if (batch[m] < g + 1) a = m + 1; else b = m; }
      hi = a; }
    int cnt = hi - lo;
    float inv = 1.0f / (float)(cnt > 1 ? cnt : 1);

    if (tid < HID) {
        float A = g_bnA[tid], B = g_bnB[tid];
        float s = 0.0f;
        for (int r = lo; r < hi; r++) {
            size_t o = (size_t)r * PITCH + tid;
            s += fmaxf(g_agg[o] * A + B, 0.0f) + g_h[o];
        }
        hg[tid] = s * inv;
    }
    __syncthreads();
    if (tid < HID2) {
        float s = b1[tid];
        for (int k = 0; k < HID; k++) s += hg[k] * W1[k * HID2 + tid];
        p[tid] = fmaxf(s, 0.0f) * W2[tid];
    }
    __syncthreads();
    if (tid == 0) {
        float s = b2[0];
        for (int j = 0; j < HID2; j++) s += p[j];
        out[g] = s;
    }
}

// ---------------- launch ----------------
extern "C" void kernel_launch(void* const* d_in, const int* in_sizes, int n_in,
                              void* d_out, int out_size) {
    const int*   x     = (const int*)  d_in[0];
    const int*   ei    = (const int*)  d_in[1];
    const int*   batch = (const int*)  d_in[2];
    const float* emb   = (const float*)d_in[3];
    const float* Wc    = (const float*)d_in[4];
    const float* bc    = (const float*)d_in[5];
    const float* gamma = (const float*)d_in[6];
    const float* beta  = (const float*)d_in[7];
    const float* W1    = (const float*)d_in[8];
    const float* b1    = (const float*)d_in[9];
    const float* W2    = (const float*)d_in[10];
    const float* b2    = (const float*)d_in[11];
    float* out = (float*)d_out;

    const int gemmBlocks   = (N_NODES + TILE_M - 1) / TILE_M;            // 782
    const int gatherBlocks = (N_NODES + 16 * NPW - 1) / (16 * NPW);      // 391

    k_deg_zero <<<(N_NODES + 255) / 256, 256>>>();
    k_deg_count<<<(N_EDGES + 255) / 256, 256>>>(ei);
    k_dis      <<<(N_NODES + 255) / 256, 256>>>();
    // layer-0 GEMM needs only x/emb -> run it 4th so ncu profiles it
    k_gemm     <<<gemmBlocks, 256>>>(Wc, x, emb, 0);
    k_scan1    <<<SCAN_NB, 1024>>>();
    k_scan2    <<<1, 64>>>();
    k_scan3    <<<SCAN_NB, 1024>>>();
    k_fill     <<<(N_EDGES + 255) / 256, 256>>>(ei);

    for (int l = 0; l < N_LAYERS; l++) {
        k_gather <<<gatherBlocks, 512>>>(bc + l * HID);
        k_bnab   <<<1, 192>>>(gamma + l * HID, beta + l * HID);
        if (l + 1 < N_LAYERS)
            k_gemm <<<gemmBlocks, 256>>>(Wc + (size_t)(l + 1) * HID * HID, x, emb, 1);
    }

    k_pool<<<N_GRAPHS, 160>>>(batch, W1, b1, W2, b2, out);
}

// round 16
// speedup vs baseline: 1.5465x; 1.5465x over previous
#include <cuda_runtime.h>

#define N_NODES 50000
#define N_EDGES 500000
#define N_GRAPHS 2000
#define HID 145
#define PITCH 148          // row pitch (16B multiple: 148*4 = 592)
#define NCH 37             // float4 chunks per row
#define WSP 160            // Ws shared pitch: 80 col-pairs
#define HID2 72
#define N_LAYERS 4
#define EPS 1e-5f
#define TILE_M 64
#define SCAN_NB 49         // ceil(50000/1024)
#define NPW 4              // nodes per warp in gather

// ---- scratch (static device globals; +64 pad for overhung tile loads) ----
__device__ __align__(16) float  g_h  [(size_t)N_NODES * PITCH + 64];
__device__ __align__(16) float  g_hw [(size_t)N_NODES * PITCH + 64];
__device__ __align__(16) float  g_agg[(size_t)N_NODES * PITCH + 64];
__device__ float  g_dis[N_NODES];
__device__ int    g_deg[N_NODES];
__device__ int    g_rowptr[N_NODES + 1];
__device__ int    g_cursor[N_NODES];
__device__ int    g_bsum[64];
__device__ int    g_csr_src[N_EDGES];
__device__ float  g_csr_w[N_EDGES];
__device__ double g_stats[2 * PITCH];
__device__ __align__(16) float g_bnA[192];
__device__ __align__(16) float g_bnB[192];

// packed f32x2 FMA (PTX-only; ptxas never auto-fuses)
__device__ __forceinline__ float2 ffma2(float2 a, float2 b, float2 c) {
    unsigned long long ua, ub, uc, ud;
    ua = *reinterpret_cast<unsigned long long*>(&a);
    ub = *reinterpret_cast<unsigned long long*>(&b);
    uc = *reinterpret_cast<unsigned long long*>(&c);
    asm("fma.rn.f32x2 %0, %1, %2, %3;" : "=l"(ud) : "l"(ua), "l"(ub), "l"(uc));
    return *reinterpret_cast<float2*>(&ud);
}

// ---------------- degree / CSR build ----------------
__global__ void k_deg_zero() {
    int i = blockIdx.x * blockDim.x + threadIdx.x;
    if (i < N_NODES) g_deg[i] = 0;
}

__global__ void k_deg_count(const int* __restrict__ ei) {
    int e = blockIdx.x * blockDim.x + threadIdx.x;
    if (e < N_EDGES) atomicAdd(&g_deg[ei[N_EDGES + e]], 1);  // target = col
}

__global__ void k_dis() {
    int i = blockIdx.x * blockDim.x + threadIdx.x;
    if (i < N_NODES) g_dis[i] = rsqrtf((float)(g_deg[i] + 1));  // +1 self loop
}

// ---- 3-phase parallel scan over degrees -> rowptr (exclusive), cursor ----
__global__ void k_scan1() {
    __shared__ int wsum[32];
    const int tid = threadIdx.x;
    const int i = blockIdx.x * 1024 + tid;
    int v = (i < N_NODES) ? g_deg[i] : 0;
    int lane = tid & 31, w = tid >> 5;
    int s = v;
#pragma unroll
    for (int o = 1; o < 32; o <<= 1) {
        int t = __shfl_up_sync(0xFFFFFFFFu, s, o);
        if (lane >= o) s += t;
    }
    if (lane == 31) wsum[w] = s;
    __syncthreads();
    if (w == 0) {
        int t = wsum[lane];
#pragma unroll
        for (int o = 1; o < 32; o <<= 1) {
            int u = __shfl_up_sync(0xFFFFFFFFu, t, o);
            if (lane >= o) t += u;
        }
        wsum[lane] = t;
    }
    __syncthreads();
    int excl = s - v + (w > 0 ? wsum[w - 1] : 0);
    if (i < N_NODES) g_rowptr[i] = excl;
    if (tid == 1023) g_bsum[blockIdx.x] = excl + v;   // block total
}

__global__ void k_scan2() {
    __shared__ int sh[64];
    int tid = threadIdx.x;
    if (tid < SCAN_NB) sh[tid] = g_bsum[tid];
    __syncthreads();
    if (tid == 0) {
        int acc = 0;
        for (int b = 0; b < SCAN_NB; b++) { int t = sh[b]; sh[b] = acc; acc += t; }
    }
    __syncthreads();
    if (tid < SCAN_NB) g_bsum[tid] = sh[tid];
}

__global__ void k_scan3() {
    int i = blockIdx.x * 1024 + threadIdx.x;
    if (i < N_NODES) {
        int v = g_rowptr[i] + g_bsum[blockIdx.x];
        g_rowptr[i] = v;
        g_cursor[i] = v;
    }
    if (i == 0) g_rowptr[N_NODES] = N_EDGES;
}

__global__ void k_fill(const int* __restrict__ ei) {
    int e = blockIdx.x * blockDim.x + threadIdx.x;
    if (e >= N_EDGES) return;
    int r = ei[e];
    int c = ei[N_EDGES + e];
    int pos = atomicAdd(&g_cursor[c], 1);
    g_csr_src[pos] = r;
    g_csr_w[pos]   = g_dis[r] * g_dis[c];
}

// ---------------- GEMM: hw = h @ Wc[l], fused A-generation ----------------
// mode 0: A = emb[x[row]]  (embedding gather; also materializes g_h)
// mode 1: A = relu(g_agg*bnA+bnB) + g_h_old  (prev layer's epilogue; updates g_h)
// Block: 64 rows x 160 cols, 256 threads. Thread: 4 rows x 5 col-pairs (f32x2).
__global__ void __launch_bounds__(256) k_gemm(const float* __restrict__ Wl,
                                              const int*   __restrict__ x,
                                              const float* __restrict__ emb,
                                              int mode) {
    __shared__ float As[TILE_M * 64];       // 16 KB
    __shared__ float Ws[64 * WSP];          // 40 KB
    const int tid  = threadIdx.x;
    const int ct   = tid & 15;
    const int rt   = tid >> 4;
    const int row0 = blockIdx.x * TILE_M;

    if (blockIdx.x == 0)
        for (int i = tid; i < 2 * PITCH; i += 256) g_stats[i] = 0.0;  // zero BN stats

    float2 acc[4][5];
#pragma unroll
    for (int r = 0; r < 4; r++)
#pragma unroll
        for (int j = 0; j < 5; j++) acc[r][j] = make_float2(0.0f, 0.0f);

#pragma unroll 1
    for (int kt = 0; kt < 160; kt += 64) {
        const int kmax = (160 - kt) < 64 ? (160 - kt) : 64;   // 64,64,32
        __syncthreads();
        // A tile [64 x 64]: 1024 float4 slots, 4 per thread
#pragma unroll
        for (int q = 0; q < 4; q++) {
            int fi   = tid + 256 * q;
            int row  = fi >> 4;
            int kq   = fi & 15;
            int col0 = kt + kq * 4;
            int r    = row0 + row;
            float4 v = make_float4(0.f, 0.f, 0.f, 0.f);
            if (r < N_NODES && col0 < 160) {
                if (mode == 0) {
                    int base = x[r] * HID;
                    v.x = (col0     < HID) ? emb[base + col0]     : 0.0f;
                    v.y = (col0 + 1 < HID) ? emb[base + col0 + 1] : 0.0f;
                    v.z = (col0 + 2 < HID) ? emb[base + col0 + 2] : 0.0f;
                    v.w = (col0 + 3 < HID) ? emb[base + col0 + 3] : 0.0f;
                    if (col0 < PITCH) *(float4*)&g_h[(size_t)r * PITCH + col0] = v;
                } else {
                    float4 va = *(const float4*)&g_agg[(size_t)r * PITCH + col0];
                    float4 vh = *(const float4*)&g_h  [(size_t)r * PITCH + col0];
                    float4 A  = *(const float4*)&g_bnA[col0];
                    float4 B  = *(const float4*)&g_bnB[col0];
                    v.x = fmaxf(va.x * A.x + B.x, 0.0f) + vh.x;
                    v.y = fmaxf(va.y * A.y + B.y, 0.0f) + vh.y;
                    v.z = fmaxf(va.z * A.z + B.z, 0.0f) + vh.z;
                    v.w = fmaxf(va.w * A.w + B.w, 0.0f) + vh.w;
                    if (col0 < PITCH) *(float4*)&g_h[(size_t)r * PITCH + col0] = v;
                }
            }
            *(float4*)&As[row * 64 + kq * 4] = v;
        }
        // W tile [kmax x 160], zero outside live range
        for (int i = tid; i < kmax * WSP; i += 256) {
            int kk = i / WSP, c = i - kk * WSP;
            int kg = kt + kk;
            Ws[i] = (kg < HID && c < HID) ? Wl[kg * HID + c] : 0.0f;
        }
        __syncthreads();

#pragma unroll 4
        for (int k4 = 0; k4 < kmax; k4 += 4) {
            float4 av0 = *(const float4*)&As[(rt * 4 + 0) * 64 + k4];
            float4 av1 = *(const float4*)&As[(rt * 4 + 1) * 64 + k4];
            float4 av2 = *(const float4*)&As[(rt * 4 + 2) * 64 + k4];
            float4 av3 = *(const float4*)&As[(rt * 4 + 3) * 64 + k4];
#pragma unroll
            for (int kk = 0; kk < 4; kk++) {
                float2 b[5];
#pragma unroll
                for (int j = 0; j < 5; j++)
                    b[j] = *(const float2*)&Ws[(k4 + kk) * WSP + 2 * ct + 32 * j];
                float a0 = ((const float*)&av0)[kk];
                float a1 = ((const float*)&av1)[kk];
                float a2 = ((const float*)&av2)[kk];
                float a3 = ((const float*)&av3)[kk];
                float2 p0 = make_float2(a0, a0), p1 = make_float2(a1, a1);
                float2 p2 = make_float2(a2, a2), p3 = make_float2(a3, a3);
#pragma unroll
                for (int j = 0; j < 5; j++) {
                    acc[0][j] = ffma2(p0, b[j], acc[0][j]);
                    acc[1][j] = ffma2(p1, b[j], acc[1][j]);
                    acc[2][j] = ffma2(p2, b[j], acc[2][j]);
                    acc[3][j] = ffma2(p3, b[j], acc[3][j]);
                }
            }
        }
    }

#pragma unroll
    for (int rr = 0; rr < 4; rr++) {
        int r = row0 + rt * 4 + rr;
        if (r >= N_NODES) continue;
#pragma unroll
        for (int j = 0; j < 5; j++) {
            int c0 = 2 * ct + 32 * j;
            if (c0 >= PITCH) continue;
            *(float2*)&g_hw[(size_t)r * PITCH + c0] = acc[rr][j];
        }
    }
}

// ------- aggregation: 4 nodes per warp, register stats, one block reduce ------
// 512 threads = 16 warps x NPW nodes = 64 nodes/block; 782 blocks.
__global__ void __launch_bounds__(512) k_gather(const float* __restrict__ bcl) {
    __shared__ float sums1[16][PITCH];
    __shared__ float sums2[16][PITCH];
    const int wib  = threadIdx.x >> 5;
    const int lane = threadIdx.x & 31;
    const int warpId = blockIdx.x * 16 + wib;
    const bool tail = lane < NCH - 32;

    float s1a[4] = {0.f, 0.f, 0.f, 0.f}, s2a[4] = {0.f, 0.f, 0.f, 0.f};
    float s1b[4] = {0.f, 0.f, 0.f, 0.f}, s2b[4] = {0.f, 0.f, 0.f, 0.f};

#pragma unroll 1
    for (int i = 0; i < NPW; i++) {
        int node = warpId * NPW + i;
        if (node < N_NODES) {
            const int beg = g_rowptr[node];
            const int end = g_rowptr[node + 1];
            float d  = g_dis[node];
            float sw = d * d;                 // self-loop weight

            const float4* own = (const float4*)g_hw + (size_t)node * NCH;

            float4 a0, a1 = make_float4(0.f, 0.f, 0.f, 0.f);
            {
                float4 v = own[lane];
                int c = lane * 4;
                a0.x = bcl[c]     + sw * v.x;
                a0.y = bcl[c + 1] + sw * v.y;
                a0.z = bcl[c + 2] + sw * v.z;
                a0.w = bcl[c + 3] + sw * v.w;
                if (tail) {
                    float4 v2 = own[32 + lane];
                    int c2 = 128 + lane * 4;
                    a1.x = (c2     < HID ? bcl[c2]     : 0.0f) + sw * v2.x;
                    a1.y = (c2 + 1 < HID ? bcl[c2 + 1] : 0.0f) + sw * v2.y;
                    a1.z = (c2 + 2 < HID ? bcl[c2 + 2] : 0.0f) + sw * v2.z;
                    a1.w = (c2 + 3 < HID ? bcl[c2 + 3] : 0.0f) + sw * v2.w;
                }
            }

            int e = beg;
            for (; e + 3 < end; e += 4) {     // 4x unroll (deg~10)
                int   s0 = g_csr_src[e],     s1 = g_csr_src[e + 1];
                int   s2 = g_csr_src[e + 2], s3 = g_csr_src[e + 3];
                float w0 = g_csr_w[e],       w1 = g_csr_w[e + 1];
                float w2 = g_csr_w[e + 2],   w3 = g_csr_w[e + 3];
                const float4* sp0 = (const float4*)g_hw + (size_t)s0 * NCH;
                const float4* sp1 = (const float4*)g_hw + (size_t)s1 * NCH;
                const float4* sp2 = (const float4*)g_hw + (size_t)s2 * NCH;
                const float4* sp3 = (const float4*)g_hw + (size_t)s3 * NCH;
                float4 v0 = sp0[lane], v1 = sp1[lane], v2 = sp2[lane], v3 = sp3[lane];
                float4 u0, u1, u2, u3;
                if (tail) { u0 = sp0[32 + lane]; u1 = sp1[32 + lane];
                            u2 = sp2[32 + lane]; u3 = sp3[32 + lane]; }
                a0.x += w0 * v0.x + w1 * v1.x + w2 * v2.x + w3 * v3.x;
                a0.y += w0 * v0.y + w1 * v1.y + w2 * v2.y + w3 * v3.y;
                a0.z += w0 * v0.z + w1 * v1.z + w2 * v2.z + w3 * v3.z;
                a0.w += w0 * v0.w + w1 * v1.w + w2 * v2.w + w3 * v3.w;
                if (tail) {
                    a1.x += w0 * u0.x + w1 * u1.x + w2 * u2.x + w3 * u3.x;
                    a1.y += w0 * u0.y + w1 * u1.y + w2 * u2.y + w3 * u3.y;
                    a1.z += w0 * u0.z + w1 * u1.z + w2 * u2.z + w3 * u3.z;
                    a1.w += w0 * u0.w + w1 * u1.w + w2 * u2.w + w3 * u3.w;
                }
            }
            for (; e < end; e++) {
                int   s0 = g_csr_src[e];
                float w0 = g_csr_w[e];
                const float4* sp0 = (const float4*)g_hw + (size_t)s0 * NCH;
                float4 v0 = sp0[lane];
                a0.x += w0 * v0.x; a0.y += w0 * v0.y; a0.z += w0 * v0.z; a0.w += w0 * v0.w;
                if (tail) {
                    float4 u0 = sp0[32 + lane];
                    a1.x += w0 * u0.x; a1.y += w0 * u0.y; a1.z += w0 * u0.z; a1.w += w0 * u0.w;
                }
            }

            float4* dst = (float4*)g_agg + (size_t)node * NCH;
            dst[lane] = a0;
            if (tail) dst[32 + lane] = a1;

            // accumulate per-lane channel stats in registers (float partials)
            s1a[0] += a0.x; s2a[0] += a0.x * a0.x;
            s1a[1] += a0.y; s2a[1] += a0.y * a0.y;
            s1a[2] += a0.z; s2a[2] += a0.z * a0.z;
            s1a[3] += a0.w; s2a[3] += a0.w * a0.w;
            if (tail) {
                s1b[0] += a1.x; s2b[0] += a1.x * a1.x;
                s1b[1] += a1.y; s2b[1] += a1.y * a1.y;
                s1b[2] += a1.z; s2b[2] += a1.z * a1.z;
                s1b[3] += a1.w; s2b[3] += a1.w * a1.w;
            }
        }
    }

    // stage per-warp partials (lane l owns channels 4l..4l+3 and 128+4l..+3)
    {
        int c = lane * 4;
#pragma unroll
        for (int j = 0; j < 4; j++) {
            sums1[wib][c + j] = s1a[j];
            sums2[wib][c + j] = s2a[j];
        }
        if (tail) {
            int c2 = 128 + lane * 4;
#pragma unroll
            for (int j = 0; j < 4; j++) {
                sums1[wib][c2 + j] = s1b[j];
                sums2[wib][c2 + j] = s2b[j];
            }
        }
    }
    __syncthreads();
    int c = threadIdx.x;
    if (c < PITCH) {
        double t1 = 0.0, t2 = 0.0;
#pragma unroll
        for (int k = 0; k < 16; k++) {
            t1 += (double)sums1[k][c];
            t2 += (double)sums2[k][c];
        }
        atomicAdd(&g_stats[c], t1);
        atomicAdd(&g_stats[PITCH + c], t2);
    }
}

__global__ void k_bnab(const float* __restrict__ gammal, const float* __restrict__ betal) {
    int c = threadIdx.x;
    if (c >= 192) return;
    if (c < HID) {
        double mu  = g_stats[c] / (double)N_NODES;
        double var = g_stats[PITCH + c] / (double)N_NODES - mu * mu;
        if (var < 0.0) var = 0.0;
        float a = gammal[c] * rsqrtf((float)var + EPS);
        g_bnA[c] = a;
        g_bnB[c] = betal[c] - (float)mu * a;
    } else {
        g_bnA[c] = 0.0f;
        g_bnB[c] = 0.0f;
    }
}

// ------- global mean pool (fused final BN apply) + MLP head -------
__global__ void k_pool(const int* __restrict__ batch,
                       const float* __restrict__ W1, const float* __restrict__ b1,
                       const float* __restrict__ W2, const float* __restrict__ b2,
                       float* __restrict__ out) {
    const int g   = blockIdx.x;
    const int tid = threadIdx.x;
    __shared__ float hg[HID];
    __shared__ float p[HID2];

    int lo, hi;
    { int a = 0, b = N_NODES;
      while (a < b) { int m = (a + b) >> 1; if (batch[m] < g) a = m + 1; else b = m; }
      lo = a; }
    { int a = lo, b = N_NODES;
      while (a < b) { int m = (a + b) >> 1; if (batch[m] < g + 1) a = m + 1; else b = m; }
      hi = a; }
    int cnt = hi - lo;
    float inv = 1.0f / (float)(cnt > 1 ? cnt : 1);

    if (tid < HID) {
        float A = g_bnA[tid], B = g_bnB[tid];
        float s = 0.0f;
        for (int r = lo; r < hi; r++) {
            size_t o = (size_t)r * PITCH + tid;
            s += fmaxf(g_agg[o] * A + B, 0.0f) + g_h[o];
        }
        hg[tid] = s * inv;
    }
    __syncthreads();
    if (tid < HID2) {
        float s = b1[tid];
        for (int k = 0; k < HID; k++) s += hg[k] * W1[k * HID2 + tid];
        p[tid] = fmaxf(s, 0.0f) * W2[tid];
    }
    __syncthreads();
    if (tid == 0) {
        float s = b2[0];
        for (int j = 0; j < HID2; j++) s += p[j];
        out[g] = s;
    }
}

// ---------------- launch ----------------
extern "C" void kernel_launch(void* const* d_in, const int* in_sizes, int n_in,
                              void* d_out, int out_size) {
    const int*   x     = (const int*)  d_in[0];
    const int*   ei    = (const int*)  d_in[1];
    const int*   batch = (const int*)  d_in[2];
    const float* emb   = (const float*)d_in[3];
    const float* Wc    = (const float*)d_in[4];
    const float* bc    = (const float*)d_in[5];
    const float* gamma = (const float*)d_in[6];
    const float* beta  = (const float*)d_in[7];
    const float* W1    = (const float*)d_in[8];
    const float* b1    = (const float*)d_in[9];
    const float* W2    = (const float*)d_in[10];
    const float* b2    = (const float*)d_in[11];
    float* out = (float*)d_out;

    const int gemmBlocks   = (N_NODES + TILE_M - 1) / TILE_M;            // 782
    const int gatherBlocks = (N_NODES + 16 * NPW - 1) / (16 * NPW);      // 782

    k_deg_zero <<<(N_NODES + 255) / 256, 256>>>();
    k_deg_count<<<(N_EDGES + 255) / 256, 256>>>(ei);
    k_dis      <<<(N_NODES + 255) / 256, 256>>>();
    // layer-0 GEMM needs only x/emb -> run it 4th so ncu profiles it
    k_gemm     <<<gemmBlocks, 256>>>(Wc, x, emb, 0);
    k_scan1    <<<SCAN_NB, 1024>>>();
    k_scan2    <<<1, 64>>>();
    k_scan3    <<<SCAN_NB, 1024>>>();
    k_fill     <<<(N_EDGES + 255) / 256, 256>>>(ei);

    for (int l = 0; l < N_LAYERS; l++) {
        k_gather <<<gatherBlocks, 512>>>(bc + l * HID);
        k_bnab   <<<1, 192>>>(gamma + l * HID, beta + l * HID);
        if (l + 1 < N_LAYERS)
            k_gemm <<<gemmBlocks, 256>>>(Wc + (size_t)(l + 1) * HID * HID, x, emb, 1);
    }

    k_pool<<<N_GRAPHS, 160>>>(batch, W1, b1, W2, b2, out);
}